// round 10
// baseline (speedup 1.0000x reference)
#include <cuda_runtime.h>
#include <cuda_fp16.h>
#include <cstdint>
#include <cstddef>

#define HWSZ 4096
#define CCH  256
#define NSLAB 32
#define NTILE 32

__device__ __half g_fph [NSLAB * CCH * HWSZ];   // feature_p in fp16
__device__ __half g_wh  [CCH * CCH];
__device__ float  g_pmax[NSLAB * NTILE * CCH];
__device__ float  g_psum[NSLAB * NTILE * CCH];
__device__ float  g_rmax[8 * CCH];
__device__ float  g_rsum[8 * CCH];
__device__ float  g_pool[NSLAB * 512];
__device__ float  g_ain_p[8 * 3 * CCH];
__device__ float  g_ain_f[8 * 4 * CCH];
__device__ float  g_q   [8 * 4 * CCH];
__device__ float  g_k   [8 * 3 * CCH];
__device__ float  g_coef[8 * 4 * 4];

__device__ __forceinline__ float siluf(float x) { return x / (1.0f + __expf(-x)); }
__device__ __forceinline__ uint32_t smem_u32(const void* p) {
    uint32_t a; asm("{ .reg .u64 t; cvta.to.shared.u64 t, %1; cvt.u32.u64 %0, t; }" : "=r"(a) : "l"(p));
    return a;
}
__device__ __forceinline__ uint32_t pack_h2(float lo, float hi) {
    __half2 h = __floats2half2_rn(lo, hi);
    return *reinterpret_cast<uint32_t*>(&h);
}
#define CPA16(dst, src) asm volatile("cp.async.cg.shared.global [%0], [%1], 16;" :: "r"(dst), "l"(src))
#define CP_COMMIT()     asm volatile("cp.async.commit_group;")
#define CP_WAIT(n)      asm volatile("cp.async.wait_group %0;" :: "n"(n))

__global__ void k_wconv(const float* __restrict__ W)
{
    const int i = blockIdx.x * 256 + threadIdx.x;
    g_wh[i] = __float2half_rn(__ldg(W + i));
}

__global__ void k_rawpool(const float* __restrict__ feat)
{
    const int id = blockIdx.x;
    const int b = id >> 8;
    const float4* s4 = (const float4*)(feat + ((size_t)((b * 4 + 3) * CCH + (id & 255))) * HWSZ);
    const int tid = threadIdx.x;
    float mx = -3.402823e38f, sm = 0.f;
#pragma unroll 4
    for (int i = tid; i < HWSZ / 4; i += 128) {
        const float4 v = __ldg(s4 + i);
        mx = fmaxf(mx, fmaxf(fmaxf(v.x, v.y), fmaxf(v.z, v.w)));
        sm += v.x + v.y + v.z + v.w;
    }
#pragma unroll
    for (int off = 16; off; off >>= 1) {
        mx = fmaxf(mx, __shfl_xor_sync(0xffffffffu, mx, off));
        sm += __shfl_xor_sync(0xffffffffu, sm, off);
    }
    __shared__ float smx[4], ssm[4];
    if ((tid & 31) == 0) { smx[tid >> 5] = mx; ssm[tid >> 5] = sm; }
    __syncthreads();
    if (tid == 0) {
        float m = smx[0], s = ssm[0];
        for (int i = 1; i < 4; i++) { m = fmaxf(m, smx[i]); s += ssm[i]; }
        g_rmax[id] = m; g_rsum[id] = s;
    }
}

// ---- fp16 mma GEMM: R8 structure (128x128 tile, 256 thr, 2 CTA/SM), fp16 store ----
#define AS_U32  (4 * 128 * 12)
#define BS_F32  (4 * 16 * 132)
#define DSMEM   (AS_U32 * 4 + BS_F32 * 4 + 4096)

__global__ __launch_bounds__(256, 2)
void k_gemm(const float* __restrict__ feat,
            const float* __restrict__ gma, const float* __restrict__ bta,
            const float* __restrict__ mu,  const float* __restrict__ var)
{
    extern __shared__ char dsm[];
    uint32_t* As = (uint32_t*)dsm;
    float*    Bsm = (float*)(dsm + AS_U32 * 4);
    float*    red_mx = (float*)(dsm + AS_U32 * 4 + BS_F32 * 4);   // [128][4]
    float*    red_sm = red_mx + 512;

    const int slab = blockIdx.z;
    const float* F = feat + (size_t)slab * CCH * HWSZ;
    __half* OUTP = g_fph + (size_t)slab * CCH * HWSZ;
    const int mB = blockIdx.y * 128, nB = blockIdx.x * 128;
    const int tid = threadIdx.x, lane = tid & 31, warp = tid >> 5;
    const int wm = (warp >> 2) * 64, wn = (warp & 3) * 32;

    const uint32_t asu = smem_u32(As), bsu = smem_u32(Bsm);
    const int aRow = tid >> 1, aHg = tid & 1;
    const uint32_t aDst = asu + ((aRow * 12 + aHg * 4) << 2);
    const __half* aSrcBase = g_wh + (size_t)(mB + aRow) * CCH + aHg * 8;
    const int bRow0 = tid >> 5, bC0 = tid & 31;
    const uint32_t bDst0 = bsu + ((bRow0 * 132 + bC0 * 4) << 2);
    const uint32_t bDst1 = bsu + (((bRow0 + 8) * 132 + bC0 * 4) << 2);

    float d[4][4][4];
#pragma unroll
    for (int i = 0; i < 4; i++)
#pragma unroll
        for (int j = 0; j < 4; j++)
#pragma unroll
            for (int r = 0; r < 4; r++) d[i][j][r] = 0.f;

#define ISSUE(s, kt) { \
        const int ko = (kt) * 16; \
        CPA16(aDst + (s) * (1536 << 2), aSrcBase + ko); \
        const float* fB = F + (size_t)ko * HWSZ + nB; \
        CPA16(bDst0 + (s) * (2112 << 2), fB + (size_t)bRow0 * HWSZ + bC0 * 4); \
        CPA16(bDst1 + (s) * (2112 << 2), fB + (size_t)(bRow0 + 8) * HWSZ + bC0 * 4); \
        CP_COMMIT(); }

    ISSUE(0, 0) ISSUE(1, 1) ISSUE(2, 2)

    for (int kt = 0; kt < 16; ++kt) {
        if (kt < 14) CP_WAIT(2); else if (kt == 14) CP_WAIT(1); else CP_WAIT(0);
        __syncthreads();
        if (kt < 13) ISSUE((kt + 3) & 3, kt + 3)

        const uint32_t* Ab = As + (kt & 3) * 1536;
        const float*    Bb = Bsm + (kt & 3) * 2112;
        uint32_t a[4][4], bb[4][2];
        const int rr = lane >> 2, cc = lane & 3;
#pragma unroll
        for (int mi = 0; mi < 4; mi++) {
            const int r = wm + mi * 16 + rr;
            a[mi][0] = Ab[r * 12 + cc];
            a[mi][1] = Ab[(r + 8) * 12 + cc];
            a[mi][2] = Ab[r * 12 + cc + 4];
            a[mi][3] = Ab[(r + 8) * 12 + cc + 4];
        }
#pragma unroll
        for (int ni = 0; ni < 4; ni++) {
            const int s = wn + ni * 8 + rr;
            bb[ni][0] = pack_h2(Bb[(2 * cc) * 132 + s],     Bb[(2 * cc + 1) * 132 + s]);
            bb[ni][1] = pack_h2(Bb[(2 * cc + 8) * 132 + s], Bb[(2 * cc + 9) * 132 + s]);
        }
#pragma unroll
        for (int mi = 0; mi < 4; mi++)
#pragma unroll
            for (int ni = 0; ni < 4; ni++)
                asm volatile(
                    "mma.sync.aligned.m16n8k16.row.col.f32.f16.f16.f32 "
                    "{%0,%1,%2,%3},{%4,%5,%6,%7},{%8,%9},{%0,%1,%2,%3};"
                    : "+f"(d[mi][ni][0]), "+f"(d[mi][ni][1]),
                      "+f"(d[mi][ni][2]), "+f"(d[mi][ni][3])
                    : "r"(a[mi][0]), "r"(a[mi][1]), "r"(a[mi][2]), "r"(a[mi][3]),
                      "r"(bb[ni][0]), "r"(bb[ni][1]));
        __syncthreads();
    }

#pragma unroll
    for (int mi = 0; mi < 4; mi++) {
        const int rb = mB + wm + mi * 16 + (lane >> 2);
#pragma unroll
        for (int rh = 0; rh < 2; rh++) {
            const int o = rb + rh * 8;
            const float sc = __ldg(gma + o) * rsqrtf(__ldg(var + o) + 1e-3f);
            const float bi = __ldg(bta + o) - __ldg(mu + o) * sc;
            float lmx = -3.402823e38f, lsm = 0.f;
#pragma unroll
            for (int ni = 0; ni < 4; ni++) {
                const int s = nB + wn + ni * 8 + (lane & 3) * 2;
                const float y0 = siluf(d[mi][ni][rh * 2 + 0] * sc + bi);
                const float y1 = siluf(d[mi][ni][rh * 2 + 1] * sc + bi);
                *(__half2*)(OUTP + (size_t)o * HWSZ + s) = __floats2half2_rn(y0, y1);
                lmx = fmaxf(lmx, fmaxf(y0, y1));
                lsm += y0 + y1;
            }
            lmx = fmaxf(lmx, __shfl_xor_sync(0xffffffffu, lmx, 1));
            lsm += __shfl_xor_sync(0xffffffffu, lsm, 1);
            lmx = fmaxf(lmx, __shfl_xor_sync(0xffffffffu, lmx, 2));
            lsm += __shfl_xor_sync(0xffffffffu, lsm, 2);
            if ((lane & 3) == 0) {
                const int ch = wm + mi * 16 + rh * 8 + (lane >> 2);
                red_mx[ch * 4 + (warp & 3)] = lmx;
                red_sm[ch * 4 + (warp & 3)] = lsm;
            }
        }
    }
    __syncthreads();
    if (tid < 128) {
        float m = red_mx[tid * 4], s = red_sm[tid * 4];
#pragma unroll
        for (int i = 1; i < 4; i++) { m = fmaxf(m, red_mx[tid * 4 + i]); s += red_sm[tid * 4 + i]; }
        const size_t idx = ((size_t)slab * NTILE + blockIdx.x) * CCH + mB + tid;
        g_pmax[idx] = m;
        g_psum[idx] = s;
    }
}

__global__ void k_poolred()
{
    const int slab = blockIdx.x, c = threadIdx.x;
    const int t = slab & 3;
    float mx, sm;
    if (t < 3) {
        const size_t base = (size_t)slab * NTILE * CCH + c;
        mx = -3.402823e38f; sm = 0.f;
#pragma unroll
        for (int i = 0; i < NTILE; i++) {
            mx = fmaxf(mx, g_pmax[base + (size_t)i * CCH]);
            sm += g_psum[base + (size_t)i * CCH];
        }
    } else {
        const int b = slab >> 2;
        mx = g_rmax[b * CCH + c];
        sm = g_rsum[b * CCH + c];
    }
    g_pool[slab * 512 + c] = mx;
    g_pool[slab * 512 + 256 + c] = sm * (1.0f / 4096.0f);
}

__global__ __launch_bounds__(256)
void k_ain(const float* __restrict__ w_in, const float* __restrict__ b_in,
           const float* __restrict__ ptc,  const float* __restrict__ ftc,
           const float* __restrict__ w_tc, const float* __restrict__ b_tc)
{
    const int b = blockIdx.x;
    __shared__ float pool[4][512];
    const int tid = threadIdx.x, lane = tid & 31, warp = tid >> 5;
    for (int i = tid; i < 2048; i += 256)
        ((float*)pool)[i] = g_pool[b * 4 * 512 + i];
    __syncthreads();

    const int o = blockIdx.y * 8 + warp;
    const float* wr = w_in + (size_t)o * 512;
    float a0 = 0.f, a1 = 0.f, a2 = 0.f, a3 = 0.f;
#pragma unroll
    for (int c = lane; c < 512; c += 32) {
        const float w = __ldg(wr + c);
        a0 += w * pool[0][c]; a1 += w * pool[1][c];
        a2 += w * pool[2][c]; a3 += w * pool[3][c];
    }
#pragma unroll
    for (int off = 16; off; off >>= 1) {
        a0 += __shfl_xor_sync(0xffffffffu, a0, off);
        a1 += __shfl_xor_sync(0xffffffffu, a1, off);
        a2 += __shfl_xor_sync(0xffffffffu, a2, off);
        a3 += __shfl_xor_sync(0xffffffffu, a3, off);
    }
    if (lane == 0) {
        const float bi = __ldg(b_in + o), wt = __ldg(w_tc + o), bt = __ldg(b_tc + o);
        g_ain_p[(b * 3 + 0) * CCH + o] = siluf(a0 + bi) + tanhf(__ldg(ptc + b * 3 + 0) * wt + bt);
        g_ain_p[(b * 3 + 1) * CCH + o] = siluf(a1 + bi) + tanhf(__ldg(ptc + b * 3 + 1) * wt + bt);
        g_ain_p[(b * 3 + 2) * CCH + o] = siluf(a2 + bi) + tanhf(__ldg(ptc + b * 3 + 2) * wt + bt);
        const float b3 = siluf(a3 + bi);
#pragma unroll
        for (int f = 0; f < 4; f++)
            g_ain_f[(b * 4 + f) * CCH + o] = b3 + tanhf(__ldg(ftc + b * 4 + f) * wt + bt);
    }
}

__global__ __launch_bounds__(256)
void k_qk2(const float* __restrict__ w_q, const float* __restrict__ b_q,
           const float* __restrict__ w_k, const float* __restrict__ b_k)
{
    const int b = blockIdx.x;
    __shared__ float ainf[4][256], ainp[3][256];
    const int tid = threadIdx.x, lane = tid & 31, warp = tid >> 5;
    for (int i = tid; i < 1024; i += 256) ((float*)ainf)[i] = g_ain_f[b * 4 * CCH + i];
    for (int i = tid; i < 768;  i += 256) ((float*)ainp)[i] = g_ain_p[b * 3 * CCH + i];
    __syncthreads();

    const int o = blockIdx.y * 8 + warp;
    const float* wqr = w_q + (size_t)o * 256;
    const float* wkr = w_k + (size_t)o * 256;
    float q0 = 0.f, q1 = 0.f, q2 = 0.f, q3 = 0.f, k0 = 0.f, k1 = 0.f, k2 = 0.f;
#pragma unroll
    for (int c = lane; c < 256; c += 32) {
        const float wq = __ldg(wqr + c), wk = __ldg(wkr + c);
        q0 += wq * ainf[0][c]; q1 += wq * ainf[1][c];
        q2 += wq * ainf[2][c]; q3 += wq * ainf[3][c];
        k0 += wk * ainp[0][c]; k1 += wk * ainp[1][c]; k2 += wk * ainp[2][c];
    }
#pragma unroll
    for (int off = 16; off; off >>= 1) {
        q0 += __shfl_xor_sync(0xffffffffu, q0, off);
        q1 += __shfl_xor_sync(0xffffffffu, q1, off);
        q2 += __shfl_xor_sync(0xffffffffu, q2, off);
        q3 += __shfl_xor_sync(0xffffffffu, q3, off);
        k0 += __shfl_xor_sync(0xffffffffu, k0, off);
        k1 += __shfl_xor_sync(0xffffffffu, k1, off);
        k2 += __shfl_xor_sync(0xffffffffu, k2, off);
    }
    if (lane == 0) {
        const float bq = __ldg(b_q + o), bk = __ldg(b_k + o);
        g_q[(b * 4 + 0) * CCH + o] = q0 + bq;
        g_q[(b * 4 + 1) * CCH + o] = q1 + bq;
        g_q[(b * 4 + 2) * CCH + o] = q2 + bq;
        g_q[(b * 4 + 3) * CCH + o] = q3 + bq;
        g_k[(b * 3 + 0) * CCH + o] = k0 + bk;
        g_k[(b * 3 + 1) * CCH + o] = k1 + bk;
        g_k[(b * 3 + 2) * CCH + o] = k2 + bk;
    }
}

__global__ __launch_bounds__(384)
void k_coef()
{
    const int b = blockIdx.x;
    const int tid = threadIdx.x, lane = tid & 31, warp = tid >> 5;
    __shared__ float aw[12];
    const int f = warp / 3, p = warp % 3;
    const float* qv = g_q + (b * 4 + f) * CCH;
    const float* kv = g_k + (b * 3 + p) * CCH;
    float acc = 0.f;
#pragma unroll
    for (int c = lane; c < 256; c += 32) acc += qv[c] * kv[c];
#pragma unroll
    for (int off = 16; off; off >>= 1)
        acc += __shfl_xor_sync(0xffffffffu, acc, off);
    if (lane == 0) aw[warp] = acc * 0.5f;
    __syncthreads();
    if (tid < 4) {
        const float a0 = aw[tid * 3 + 0], a1 = aw[tid * 3 + 1], a2 = aw[tid * 3 + 2];
        g_coef[(b * 4 + tid) * 4 + 0] = -a0;
        g_coef[(b * 4 + tid) * 4 + 1] = -a1;
        g_coef[(b * 4 + tid) * 4 + 2] = -a2;
        g_coef[(b * 4 + tid) * 4 + 3] = a0 + a1 + a2;
    }
}

// out: each thread handles 8 consecutive elements (fp16 fp reads), all 4 f's
__global__ __launch_bounds__(256)
void k_out(const float* __restrict__ feat, const float* __restrict__ p_attn,
           float* __restrict__ out)
{
    __shared__ float scoef[128];
    if (threadIdx.x < 128) scoef[threadIdx.x] = g_coef[threadIdx.x];
    __syncthreads();
    const int id = blockIdx.x * 256 + threadIdx.x;   // 8-elem group index
    const int b = id >> 17;
    const int rem = id & 0x1FFFF;
    const int c = rem >> 9;
    const uint4* h4 = (const uint4*)g_fph;

    float p[4][8];
#pragma unroll
    for (int t = 0; t < 4; t++) {
        const uint4 u = __ldg(h4 + ((size_t)(b * 4 + t) << 17) + rem);
        const uint32_t w[4] = {u.x, u.y, u.z, u.w};
#pragma unroll
        for (int j = 0; j < 4; j++) {
            const float2 f2 = __half22float2(*(const __half2*)&w[j]);
            p[t][2 * j] = f2.x; p[t][2 * j + 1] = f2.y;
        }
    }
    const float4* lf = (const float4*)(feat + (((size_t)(b * 4 + 3) << 17) + rem) * 8);
    const float4 l0 = __ldg(lf), l1 = __ldg(lf + 1);
    const float last[8] = {l0.x, l0.y, l0.z, l0.w, l1.x, l1.y, l1.z, l1.w};
    const float ps = __ldg(p_attn + c) * (1.0f / 3.0f);

#pragma unroll
    for (int f = 0; f < 4; f++) {
        const float* cf = scoef + (b * 4 + f) * 4;
        const float c0 = cf[0], c1 = cf[1], c2 = cf[2], c3 = cf[3];
        float r[8];
#pragma unroll
        for (int j = 0; j < 8; j++)
            r[j] = last[j] + ps * (c0 * p[0][j] + c1 * p[1][j] + c2 * p[2][j] + c3 * p[3][j]);
        float4* o4 = (float4*)(out + (((size_t)(b * 4 + f) << 17) + rem) * 8);
        o4[0] = make_float4(r[0], r[1], r[2], r[3]);
        o4[1] = make_float4(r[4], r[5], r[6], r[7]);
    }
}

extern "C" void kernel_launch(void* const* d_in, const int* in_sizes, int n_in,
                              void* d_out, int out_size)
{
    (void)in_sizes; (void)n_in; (void)out_size;
    const float* feature = (const float*)d_in[0];
    const float* ptc     = (const float*)d_in[1];
    const float* ftc     = (const float*)d_in[2];
    const float* w_tc    = (const float*)d_in[3];
    const float* b_tc    = (const float*)d_in[4];
    const float* w_in    = (const float*)d_in[5];
    const float* b_in    = (const float*)d_in[6];
    const float* conv_w  = (const float*)d_in[7];
    const float* gma     = (const float*)d_in[8];
    const float* bta     = (const float*)d_in[9];
    const float* mu      = (const float*)d_in[10];
    const float* var     = (const float*)d_in[11];
    const float* w_q     = (const float*)d_in[12];
    const float* b_q     = (const float*)d_in[13];
    const float* w_k     = (const float*)d_in[14];
    const float* b_k     = (const float*)d_in[15];
    const float* p_attn  = (const float*)d_in[16];

    cudaFuncSetAttribute(k_gemm, cudaFuncAttributeMaxDynamicSharedMemorySize, DSMEM);

    k_wconv<<<256, 256>>>(conv_w);
    k_rawpool<<<8 * CCH, 128>>>(feature);
    dim3 g1(NTILE, 2, NSLAB);
    k_gemm<<<g1, 256, DSMEM>>>(feature, gma, bta, mu, var);
    k_poolred<<<NSLAB, 256>>>();
    dim3 g2(8, 32);
    k_ain<<<g2, 256>>>(w_in, b_in, ptc, ftc, w_tc, b_tc);
    k_qk2<<<g2, 256>>>(w_q, b_q, w_k, b_k);
    k_coef<<<8, 384>>>();
    k_out<<<4096, 256>>>(feature, p_attn, (float*)d_out);
}

// round 11
// speedup vs baseline: 1.2206x; 1.2206x over previous
#include <cuda_runtime.h>
#include <cuda_fp16.h>
#include <cstdint>
#include <cstddef>

#define HWSZ 4096
#define CCH  256
#define NSLAB 32
#define NTILE 32

__device__ float  g_fp  [NSLAB * CCH * HWSZ];
__device__ __half g_wh  [CCH * CCH];
__device__ float  g_pmax[NSLAB * NTILE * CCH];
__device__ float  g_psum[NSLAB * NTILE * CCH];
__device__ float  g_rmax[8 * CCH];
__device__ float  g_rsum[8 * CCH];
__device__ float  g_pool[NSLAB * 512];
__device__ float  g_ain_p[8 * 3 * CCH];
__device__ float  g_ain_f[8 * 4 * CCH];
__device__ float  g_q   [8 * 4 * CCH];
__device__ float  g_k   [8 * 3 * CCH];
__device__ float  g_coef[8 * 4 * 4];

__device__ __forceinline__ float siluf(float x) { return x / (1.0f + __expf(-x)); }
__device__ __forceinline__ uint32_t smem_u32(const void* p) {
    uint32_t a; asm("{ .reg .u64 t; cvta.to.shared.u64 t, %1; cvt.u32.u64 %0, t; }" : "=r"(a) : "l"(p));
    return a;
}
__device__ __forceinline__ uint32_t pack_h2(float lo, float hi) {
    __half2 h = __floats2half2_rn(lo, hi);
    return *reinterpret_cast<uint32_t*>(&h);
}
#define CPA16(dst, src) asm volatile("cp.async.cg.shared.global [%0], [%1], 16;" :: "r"(dst), "l"(src))
#define CP_COMMIT()     asm volatile("cp.async.commit_group;")
#define CP_WAIT(n)      asm volatile("cp.async.wait_group %0;" :: "n"(n))

__global__ void k_wconv(const float* __restrict__ W)
{
    const int i = blockIdx.x * 256 + threadIdx.x;
    g_wh[i] = __float2half_rn(__ldg(W + i));
}

__global__ void k_rawpool(const float* __restrict__ feat)
{
    const int id = blockIdx.x;
    const int b = id >> 8;
    const float4* s4 = (const float4*)(feat + ((size_t)((b * 4 + 3) * CCH + (id & 255))) * HWSZ);
    const int tid = threadIdx.x;
    float mx = -3.402823e38f, sm = 0.f;
#pragma unroll 4
    for (int i = tid; i < HWSZ / 4; i += 128) {
        const float4 v = __ldg(s4 + i);
        mx = fmaxf(mx, fmaxf(fmaxf(v.x, v.y), fmaxf(v.z, v.w)));
        sm += v.x + v.y + v.z + v.w;
    }
#pragma unroll
    for (int off = 16; off; off >>= 1) {
        mx = fmaxf(mx, __shfl_xor_sync(0xffffffffu, mx, off));
        sm += __shfl_xor_sync(0xffffffffu, sm, off);
    }
    __shared__ float smx[4], ssm[4];
    if ((tid & 31) == 0) { smx[tid >> 5] = mx; ssm[tid >> 5] = sm; }
    __syncthreads();
    if (tid == 0) {
        float m = smx[0], s = ssm[0];
        for (int i = 1; i < 4; i++) { m = fmaxf(m, smx[i]); s += ssm[i]; }
        g_rmax[id] = m; g_rsum[id] = s;
    }
}

// ---- fp16 mma GEMM (R8 structure), single-barrier mainloop, streaming stores ----
#define AS_U32  (4 * 128 * 12)
#define BS_F32  (4 * 16 * 132)
#define DSMEM   (AS_U32 * 4 + BS_F32 * 4 + 4096)

__global__ __launch_bounds__(256, 2)
void k_gemm(const float* __restrict__ feat,
            const float* __restrict__ gma, const float* __restrict__ bta,
            const float* __restrict__ mu,  const float* __restrict__ var)
{
    extern __shared__ char dsm[];
    uint32_t* As = (uint32_t*)dsm;
    float*    Bsm = (float*)(dsm + AS_U32 * 4);
    float*    red_mx = (float*)(dsm + AS_U32 * 4 + BS_F32 * 4);   // [128][4]
    float*    red_sm = red_mx + 512;

    const int slab = blockIdx.z;
    const float* F = feat + (size_t)slab * CCH * HWSZ;
    float* OUTP = g_fp + (size_t)slab * CCH * HWSZ;
    const int mB = blockIdx.y * 128, nB = blockIdx.x * 128;
    const int tid = threadIdx.x, lane = tid & 31, warp = tid >> 5;
    const int wm = (warp >> 2) * 64, wn = (warp & 3) * 32;

    const uint32_t asu = smem_u32(As), bsu = smem_u32(Bsm);
    const int aRow = tid >> 1, aHg = tid & 1;
    const uint32_t aDst = asu + ((aRow * 12 + aHg * 4) << 2);
    const __half* aSrcBase = g_wh + (size_t)(mB + aRow) * CCH + aHg * 8;
    const int bRow0 = tid >> 5, bC0 = tid & 31;
    const uint32_t bDst0 = bsu + ((bRow0 * 132 + bC0 * 4) << 2);
    const uint32_t bDst1 = bsu + (((bRow0 + 8) * 132 + bC0 * 4) << 2);

    float d[4][4][4];
#pragma unroll
    for (int i = 0; i < 4; i++)
#pragma unroll
        for (int j = 0; j < 4; j++)
#pragma unroll
            for (int r = 0; r < 4; r++) d[i][j][r] = 0.f;

#define ISSUE(s, kt) { \
        const int ko = (kt) * 16; \
        CPA16(aDst + (s) * (1536 << 2), aSrcBase + ko); \
        const float* fB = F + (size_t)ko * HWSZ + nB; \
        CPA16(bDst0 + (s) * (2112 << 2), fB + (size_t)bRow0 * HWSZ + bC0 * 4); \
        CPA16(bDst1 + (s) * (2112 << 2), fB + (size_t)(bRow0 + 8) * HWSZ + bC0 * 4); \
        CP_COMMIT(); }

    ISSUE(0, 0) ISSUE(1, 1) ISSUE(2, 2)

    for (int kt = 0; kt < 16; ++kt) {
        if (kt < 14) CP_WAIT(2); else if (kt == 14) CP_WAIT(1); else CP_WAIT(0);
        __syncthreads();   // single barrier: all warps finished compute(kt-1) AND group kt visible
        if (kt < 13) ISSUE((kt + 3) & 3, kt + 3)

        const uint32_t* Ab = As + (kt & 3) * 1536;
        const float*    Bb = Bsm + (kt & 3) * 2112;
        uint32_t a[4][4], bb[4][2];
        const int rr = lane >> 2, cc = lane & 3;
#pragma unroll
        for (int mi = 0; mi < 4; mi++) {
            const int r = wm + mi * 16 + rr;
            a[mi][0] = Ab[r * 12 + cc];
            a[mi][1] = Ab[(r + 8) * 12 + cc];
            a[mi][2] = Ab[r * 12 + cc + 4];
            a[mi][3] = Ab[(r + 8) * 12 + cc + 4];
        }
#pragma unroll
        for (int ni = 0; ni < 4; ni++) {
            const int s = wn + ni * 8 + rr;
            bb[ni][0] = pack_h2(Bb[(2 * cc) * 132 + s],     Bb[(2 * cc + 1) * 132 + s]);
            bb[ni][1] = pack_h2(Bb[(2 * cc + 8) * 132 + s], Bb[(2 * cc + 9) * 132 + s]);
        }
#pragma unroll
        for (int mi = 0; mi < 4; mi++)
#pragma unroll
            for (int ni = 0; ni < 4; ni++)
                asm volatile(
                    "mma.sync.aligned.m16n8k16.row.col.f32.f16.f16.f32 "
                    "{%0,%1,%2,%3},{%4,%5,%6,%7},{%8,%9},{%0,%1,%2,%3};"
                    : "+f"(d[mi][ni][0]), "+f"(d[mi][ni][1]),
                      "+f"(d[mi][ni][2]), "+f"(d[mi][ni][3])
                    : "r"(a[mi][0]), "r"(a[mi][1]), "r"(a[mi][2]), "r"(a[mi][3]),
                      "r"(bb[ni][0]), "r"(bb[ni][1]));
    }

#pragma unroll
    for (int mi = 0; mi < 4; mi++) {
        const int rb = mB + wm + mi * 16 + (lane >> 2);
#pragma unroll
        for (int rh = 0; rh < 2; rh++) {
            const int o = rb + rh * 8;
            const float sc = __ldg(gma + o) * rsqrtf(__ldg(var + o) + 1e-3f);
            const float bi = __ldg(bta + o) - __ldg(mu + o) * sc;
            float lmx = -3.402823e38f, lsm = 0.f;
#pragma unroll
            for (int ni = 0; ni < 4; ni++) {
                const int s = nB + wn + ni * 8 + (lane & 3) * 2;
                const float y0 = siluf(d[mi][ni][rh * 2 + 0] * sc + bi);
                const float y1 = siluf(d[mi][ni][rh * 2 + 1] * sc + bi);
                float2 v; v.x = y0; v.y = y1;
                __stcs((float2*)(OUTP + (size_t)o * HWSZ + s), v);
                lmx = fmaxf(lmx, fmaxf(y0, y1));
                lsm += y0 + y1;
            }
            lmx = fmaxf(lmx, __shfl_xor_sync(0xffffffffu, lmx, 1));
            lsm += __shfl_xor_sync(0xffffffffu, lsm, 1);
            lmx = fmaxf(lmx, __shfl_xor_sync(0xffffffffu, lmx, 2));
            lsm += __shfl_xor_sync(0xffffffffu, lsm, 2);
            if ((lane & 3) == 0) {
                const int ch = wm + mi * 16 + rh * 8 + (lane >> 2);
                red_mx[ch * 4 + (warp & 3)] = lmx;
                red_sm[ch * 4 + (warp & 3)] = lsm;
            }
        }
    }
    __syncthreads();
    if (tid < 128) {
        float m = red_mx[tid * 4], s = red_sm[tid * 4];
#pragma unroll
        for (int i = 1; i < 4; i++) { m = fmaxf(m, red_mx[tid * 4 + i]); s += red_sm[tid * 4 + i]; }
        const size_t idx = ((size_t)slab * NTILE + blockIdx.x) * CCH + mB + tid;
        g_pmax[idx] = m;
        g_psum[idx] = s;
    }
}

// grid (NSLAB, 2), 128 threads: c = blockIdx.y*128 + tid
__global__ void k_poolred()
{
    const int slab = blockIdx.x;
    const int c = blockIdx.y * 128 + threadIdx.x;
    const int t = slab & 3;
    float mx, sm;
    if (t < 3) {
        const size_t base = (size_t)slab * NTILE * CCH + c;
        mx = -3.402823e38f; sm = 0.f;
#pragma unroll
        for (int i = 0; i < NTILE; i++) {
            mx = fmaxf(mx, g_pmax[base + (size_t)i * CCH]);
            sm += g_psum[base + (size_t)i * CCH];
        }
    } else {
        const int b = slab >> 2;
        mx = g_rmax[b * CCH + c];
        sm = g_rsum[b * CCH + c];
    }
    g_pool[slab * 512 + c] = mx;
    g_pool[slab * 512 + 256 + c] = sm * (1.0f / 4096.0f);
}

__global__ __launch_bounds__(256)
void k_ain(const float* __restrict__ w_in, const float* __restrict__ b_in,
           const float* __restrict__ ptc,  const float* __restrict__ ftc,
           const float* __restrict__ w_tc, const float* __restrict__ b_tc)
{
    const int b = blockIdx.x;
    __shared__ float pool[4][512];
    const int tid = threadIdx.x, lane = tid & 31, warp = tid >> 5;
    for (int i = tid; i < 2048; i += 256)
        ((float*)pool)[i] = g_pool[b * 4 * 512 + i];
    __syncthreads();

    const int o = blockIdx.y * 8 + warp;
    const float* wr = w_in + (size_t)o * 512;
    float a0 = 0.f, a1 = 0.f, a2 = 0.f, a3 = 0.f;
#pragma unroll
    for (int c = lane; c < 512; c += 32) {
        const float w = __ldg(wr + c);
        a0 += w * pool[0][c]; a1 += w * pool[1][c];
        a2 += w * pool[2][c]; a3 += w * pool[3][c];
    }
#pragma unroll
    for (int off = 16; off; off >>= 1) {
        a0 += __shfl_xor_sync(0xffffffffu, a0, off);
        a1 += __shfl_xor_sync(0xffffffffu, a1, off);
        a2 += __shfl_xor_sync(0xffffffffu, a2, off);
        a3 += __shfl_xor_sync(0xffffffffu, a3, off);
    }
    if (lane == 0) {
        const float bi = __ldg(b_in + o), wt = __ldg(w_tc + o), bt = __ldg(b_tc + o);
        g_ain_p[(b * 3 + 0) * CCH + o] = siluf(a0 + bi) + tanhf(__ldg(ptc + b * 3 + 0) * wt + bt);
        g_ain_p[(b * 3 + 1) * CCH + o] = siluf(a1 + bi) + tanhf(__ldg(ptc + b * 3 + 1) * wt + bt);
        g_ain_p[(b * 3 + 2) * CCH + o] = siluf(a2 + bi) + tanhf(__ldg(ptc + b * 3 + 2) * wt + bt);
        const float b3 = siluf(a3 + bi);
#pragma unroll
        for (int f = 0; f < 4; f++)
            g_ain_f[(b * 4 + f) * CCH + o] = b3 + tanhf(__ldg(ftc + b * 4 + f) * wt + bt);
    }
}

__global__ __launch_bounds__(256)
void k_qk2(const float* __restrict__ w_q, const float* __restrict__ b_q,
           const float* __restrict__ w_k, const float* __restrict__ b_k)
{
    const int b = blockIdx.x;
    __shared__ float ainf[4][256], ainp[3][256];
    const int tid = threadIdx.x, lane = tid & 31, warp = tid >> 5;
    for (int i = tid; i < 1024; i += 256) ((float*)ainf)[i] = g_ain_f[b * 4 * CCH + i];
    for (int i = tid; i < 768;  i += 256) ((float*)ainp)[i] = g_ain_p[b * 3 * CCH + i];
    __syncthreads();

    const int o = blockIdx.y * 8 + warp;
    const float* wqr = w_q + (size_t)o * 256;
    const float* wkr = w_k + (size_t)o * 256;
    float q0 = 0.f, q1 = 0.f, q2 = 0.f, q3 = 0.f, k0 = 0.f, k1 = 0.f, k2 = 0.f;
#pragma unroll
    for (int c = lane; c < 256; c += 32) {
        const float wq = __ldg(wqr + c), wk = __ldg(wkr + c);
        q0 += wq * ainf[0][c]; q1 += wq * ainf[1][c];
        q2 += wq * ainf[2][c]; q3 += wq * ainf[3][c];
        k0 += wk * ainp[0][c]; k1 += wk * ainp[1][c]; k2 += wk * ainp[2][c];
    }
#pragma unroll
    for (int off = 16; off; off >>= 1) {
        q0 += __shfl_xor_sync(0xffffffffu, q0, off);
        q1 += __shfl_xor_sync(0xffffffffu, q1, off);
        q2 += __shfl_xor_sync(0xffffffffu, q2, off);
        q3 += __shfl_xor_sync(0xffffffffu, q3, off);
        k0 += __shfl_xor_sync(0xffffffffu, k0, off);
        k1 += __shfl_xor_sync(0xffffffffu, k1, off);
        k2 += __shfl_xor_sync(0xffffffffu, k2, off);
    }
    if (lane == 0) {
        const float bq = __ldg(b_q + o), bk = __ldg(b_k + o);
        g_q[(b * 4 + 0) * CCH + o] = q0 + bq;
        g_q[(b * 4 + 1) * CCH + o] = q1 + bq;
        g_q[(b * 4 + 2) * CCH + o] = q2 + bq;
        g_q[(b * 4 + 3) * CCH + o] = q3 + bq;
        g_k[(b * 3 + 0) * CCH + o] = k0 + bk;
        g_k[(b * 3 + 1) * CCH + o] = k1 + bk;
        g_k[(b * 3 + 2) * CCH + o] = k2 + bk;
    }
}

__global__ __launch_bounds__(384)
void k_coef()
{
    const int b = blockIdx.x;
    const int tid = threadIdx.x, lane = tid & 31, warp = tid >> 5;
    __shared__ float aw[12];
    const int f = warp / 3, p = warp % 3;
    const float* qv = g_q + (b * 4 + f) * CCH;
    const float* kv = g_k + (b * 3 + p) * CCH;
    float acc = 0.f;
#pragma unroll
    for (int c = lane; c < 256; c += 32) acc += qv[c] * kv[c];
#pragma unroll
    for (int off = 16; off; off >>= 1)
        acc += __shfl_xor_sync(0xffffffffu, acc, off);
    if (lane == 0) aw[warp] = acc * 0.5f;
    __syncthreads();
    if (tid < 4) {
        const float a0 = aw[tid * 3 + 0], a1 = aw[tid * 3 + 1], a2 = aw[tid * 3 + 2];
        g_coef[(b * 4 + tid) * 4 + 0] = -a0;
        g_coef[(b * 4 + tid) * 4 + 1] = -a1;
        g_coef[(b * 4 + tid) * 4 + 2] = -a2;
        g_coef[(b * 4 + tid) * 4 + 3] = a0 + a1 + a2;
    }
}

__global__ __launch_bounds__(256)
void k_out(const float* __restrict__ feat, const float* __restrict__ p_attn,
           float* __restrict__ out)
{
    __shared__ float scoef[128];
    if (threadIdx.x < 128) scoef[threadIdx.x] = g_coef[threadIdx.x];
    __syncthreads();
    const int id = blockIdx.x * 256 + threadIdx.x;
    const int b = id >> 18;
    const int rem = id & 0x3FFFF;
    const int c = rem >> 10;
    const float4* f4fp = (const float4*)g_fp;
    const float4* f4ft = (const float4*)feat;
    const float4 last = __ldg(f4ft + ((size_t)(b * 4 + 3) << 18) + rem);
    const float4 p0 = __ldcs(f4fp + ((size_t)(b * 4 + 0) << 18) + rem);
    const float4 p1 = __ldcs(f4fp + ((size_t)(b * 4 + 1) << 18) + rem);
    const float4 p2 = __ldcs(f4fp + ((size_t)(b * 4 + 2) << 18) + rem);
    const float4 p3 = __ldcs(f4fp + ((size_t)(b * 4 + 3) << 18) + rem);
    const float ps = __ldg(p_attn + c) * (1.0f / 3.0f);
    float4* o4 = (float4*)out;
#pragma unroll
    for (int f = 0; f < 4; f++) {
        const float* cf = scoef + (b * 4 + f) * 4;
        const float c0 = cf[0], c1 = cf[1], c2 = cf[2], c3 = cf[3];
        float4 r;
        r.x = last.x + ps * (c0 * p0.x + c1 * p1.x + c2 * p2.x + c3 * p3.x);
        r.y = last.y + ps * (c0 * p0.y + c1 * p1.y + c2 * p2.y + c3 * p3.y);
        r.z = last.z + ps * (c0 * p0.z + c1 * p1.z + c2 * p2.z + c3 * p3.z);
        r.w = last.w + ps * (c0 * p0.w + c1 * p1.w + c2 * p2.w + c3 * p3.w);
        __stcs(o4 + (((size_t)(b * 4 + f) << 18) + rem), r);
    }
}

extern "C" void kernel_launch(void* const* d_in, const int* in_sizes, int n_in,
                              void* d_out, int out_size)
{
    (void)in_sizes; (void)n_in; (void)out_size;
    const float* feature = (const float*)d_in[0];
    const float* ptc     = (const float*)d_in[1];
    const float* ftc     = (const float*)d_in[2];
    const float* w_tc    = (const float*)d_in[3];
    const float* b_tc    = (const float*)d_in[4];
    const float* w_in    = (const float*)d_in[5];
    const float* b_in    = (const float*)d_in[6];
    const float* conv_w  = (const float*)d_in[7];
    const float* gma     = (const float*)d_in[8];
    const float* bta     = (const float*)d_in[9];
    const float* mu      = (const float*)d_in[10];
    const float* var     = (const float*)d_in[11];
    const float* w_q     = (const float*)d_in[12];
    const float* b_q     = (const float*)d_in[13];
    const float* w_k     = (const float*)d_in[14];
    const float* b_k     = (const float*)d_in[15];
    const float* p_attn  = (const float*)d_in[16];

    cudaFuncSetAttribute(k_gemm, cudaFuncAttributeMaxDynamicSharedMemorySize, DSMEM);

    k_wconv<<<256, 256>>>(conv_w);
    k_rawpool<<<8 * CCH, 128>>>(feature);
    dim3 g1(NTILE, 2, NSLAB);
    k_gemm<<<g1, 256, DSMEM>>>(feature, gma, bta, mu, var);
    dim3 gp(NSLAB, 2);
    k_poolred<<<gp, 128>>>();
    dim3 g2(8, 32);
    k_ain<<<g2, 256>>>(w_in, b_in, ptc, ftc, w_tc, b_tc);
    k_qk2<<<g2, 256>>>(w_q, b_q, w_k, b_k);
    k_coef<<<8, 384>>>();
    k_out<<<8192, 256>>>(feature, p_attn, (float*)d_out);
}

// round 12
// speedup vs baseline: 1.4584x; 1.1948x over previous
#include <cuda_runtime.h>
#include <cuda_fp16.h>
#include <cstdint>
#include <cstddef>

#define HWSZ 4096
#define CCH  256
#define NSLAB 32
#define NTILE 32

__device__ float  g_fp  [NSLAB * CCH * HWSZ];
__device__ __half g_wh  [CCH * CCH];
__device__ float  g_pmax[NSLAB * NTILE * CCH];
__device__ float  g_psum[NSLAB * NTILE * CCH];
__device__ float  g_rmax[8 * CCH];
__device__ float  g_rsum[8 * CCH];
__device__ float  g_pool[NSLAB * 512];
__device__ float  g_ain_p[8 * 3 * CCH];
__device__ float  g_ain_f[8 * 4 * CCH];
__device__ float  g_q   [8 * 4 * CCH];
__device__ float  g_k   [8 * 3 * CCH];
__device__ float  g_coef[8 * 4 * 4];

__device__ __forceinline__ float siluf(float x) { return x / (1.0f + __expf(-x)); }
__device__ __forceinline__ uint32_t smem_u32(const void* p) {
    uint32_t a; asm("{ .reg .u64 t; cvta.to.shared.u64 t, %1; cvt.u32.u64 %0, t; }" : "=r"(a) : "l"(p));
    return a;
}
__device__ __forceinline__ uint32_t pack_h2(float lo, float hi) {
    __half2 h = __floats2half2_rn(lo, hi);
    return *reinterpret_cast<uint32_t*>(&h);
}
#define CPA16(dst, src) asm volatile("cp.async.cg.shared.global [%0], [%1], 16;" :: "r"(dst), "l"(src))
#define CP_COMMIT()     asm volatile("cp.async.commit_group;")
#define CP_WAIT(n)      asm volatile("cp.async.wait_group %0;" :: "n"(n))

__global__ void k_wconv(const float* __restrict__ W)
{
    const int i = blockIdx.x * 256 + threadIdx.x;
    g_wh[i] = __float2half_rn(__ldg(W + i));
}

__global__ void k_rawpool(const float* __restrict__ feat)
{
    const int id = blockIdx.x;
    const int b = id >> 8;
    const float4* s4 = (const float4*)(feat + ((size_t)((b * 4 + 3) * CCH + (id & 255))) * HWSZ);
    const int tid = threadIdx.x;
    float mx = -3.402823e38f, sm = 0.f;
#pragma unroll 4
    for (int i = tid; i < HWSZ / 4; i += 128) {
        const float4 v = __ldg(s4 + i);
        mx = fmaxf(mx, fmaxf(fmaxf(v.x, v.y), fmaxf(v.z, v.w)));
        sm += v.x + v.y + v.z + v.w;
    }
#pragma unroll
    for (int off = 16; off; off >>= 1) {
        mx = fmaxf(mx, __shfl_xor_sync(0xffffffffu, mx, off));
        sm += __shfl_xor_sync(0xffffffffu, sm, off);
    }
    __shared__ float smx[4], ssm[4];
    if ((tid & 31) == 0) { smx[tid >> 5] = mx; ssm[tid >> 5] = sm; }
    __syncthreads();
    if (tid == 0) {
        float m = smx[0], s = ssm[0];
        for (int i = 1; i < 4; i++) { m = fmaxf(m, smx[i]); s += ssm[i]; }
        g_rmax[id] = m; g_rsum[id] = s;
    }
}

// ---- fp16 mma GEMM (R8 structure), single barrier per kt ----
#define AS_U32  (4 * 128 * 12)
#define BS_F32  (4 * 16 * 132)
#define DSMEM   (AS_U32 * 4 + BS_F32 * 4 + 4096)

__global__ __launch_bounds__(256, 2)
void k_gemm(const float* __restrict__ feat,
            const float* __restrict__ gma, const float* __restrict__ bta,
            const float* __restrict__ mu,  const float* __restrict__ var)
{
    extern __shared__ char dsm[];
    uint32_t* As = (uint32_t*)dsm;
    float*    Bsm = (float*)(dsm + AS_U32 * 4);
    float*    red_mx = (float*)(dsm + AS_U32 * 4 + BS_F32 * 4);   // [128][4]
    float*    red_sm = red_mx + 512;

    const int slab = blockIdx.z;
    const float* F = feat + (size_t)slab * CCH * HWSZ;
    float* OUTP = g_fp + (size_t)slab * CCH * HWSZ;
    const int mB = blockIdx.y * 128, nB = blockIdx.x * 128;
    const int tid = threadIdx.x, lane = tid & 31, warp = tid >> 5;
    const int wm = (warp >> 2) * 64, wn = (warp & 3) * 32;

    const uint32_t asu = smem_u32(As), bsu = smem_u32(Bsm);
    const int aRow = tid >> 1, aHg = tid & 1;
    const uint32_t aDst = asu + ((aRow * 12 + aHg * 4) << 2);
    const __half* aSrcBase = g_wh + (size_t)(mB + aRow) * CCH + aHg * 8;
    const int bRow0 = tid >> 5, bC0 = tid & 31;
    const uint32_t bDst0 = bsu + ((bRow0 * 132 + bC0 * 4) << 2);
    const uint32_t bDst1 = bsu + (((bRow0 + 8) * 132 + bC0 * 4) << 2);

    float d[4][4][4];
#pragma unroll
    for (int i = 0; i < 4; i++)
#pragma unroll
        for (int j = 0; j < 4; j++)
#pragma unroll
            for (int r = 0; r < 4; r++) d[i][j][r] = 0.f;

#define ISSUE(s, kt) { \
        const int ko = (kt) * 16; \
        CPA16(aDst + (s) * (1536 << 2), aSrcBase + ko); \
        const float* fB = F + (size_t)ko * HWSZ + nB; \
        CPA16(bDst0 + (s) * (2112 << 2), fB + (size_t)bRow0 * HWSZ + bC0 * 4); \
        CPA16(bDst1 + (s) * (2112 << 2), fB + (size_t)(bRow0 + 8) * HWSZ + bC0 * 4); \
        CP_COMMIT(); }

    ISSUE(0, 0) ISSUE(1, 1) ISSUE(2, 2)

    for (int kt = 0; kt < 16; ++kt) {
        if (kt < 14) CP_WAIT(2); else if (kt == 14) CP_WAIT(1); else CP_WAIT(0);
        __syncthreads();   // all warps finished compute(kt-1); group kt visible
        if (kt < 13) ISSUE((kt + 3) & 3, kt + 3)

        const uint32_t* Ab = As + (kt & 3) * 1536;
        const float*    Bb = Bsm + (kt & 3) * 2112;
        uint32_t a[4][4], bb[4][2];
        const int rr = lane >> 2, cc = lane & 3;
#pragma unroll
        for (int mi = 0; mi < 4; mi++) {
            const int r = wm + mi * 16 + rr;
            a[mi][0] = Ab[r * 12 + cc];
            a[mi][1] = Ab[(r + 8) * 12 + cc];
            a[mi][2] = Ab[r * 12 + cc + 4];
            a[mi][3] = Ab[(r + 8) * 12 + cc + 4];
        }
#pragma unroll
        for (int ni = 0; ni < 4; ni++) {
            const int s = wn + ni * 8 + rr;
            bb[ni][0] = pack_h2(Bb[(2 * cc) * 132 + s],     Bb[(2 * cc + 1) * 132 + s]);
            bb[ni][1] = pack_h2(Bb[(2 * cc + 8) * 132 + s], Bb[(2 * cc + 9) * 132 + s]);
        }
#pragma unroll
        for (int mi = 0; mi < 4; mi++)
#pragma unroll
            for (int ni = 0; ni < 4; ni++)
                asm volatile(
                    "mma.sync.aligned.m16n8k16.row.col.f32.f16.f16.f32 "
                    "{%0,%1,%2,%3},{%4,%5,%6,%7},{%8,%9},{%0,%1,%2,%3};"
                    : "+f"(d[mi][ni][0]), "+f"(d[mi][ni][1]),
                      "+f"(d[mi][ni][2]), "+f"(d[mi][ni][3])
                    : "r"(a[mi][0]), "r"(a[mi][1]), "r"(a[mi][2]), "r"(a[mi][3]),
                      "r"(bb[ni][0]), "r"(bb[ni][1]));
    }

#pragma unroll
    for (int mi = 0; mi < 4; mi++) {
        const int rb = mB + wm + mi * 16 + (lane >> 2);
#pragma unroll
        for (int rh = 0; rh < 2; rh++) {
            const int o = rb + rh * 8;
            const float sc = __ldg(gma + o) * rsqrtf(__ldg(var + o) + 1e-3f);
            const float bi = __ldg(bta + o) - __ldg(mu + o) * sc;
            float lmx = -3.402823e38f, lsm = 0.f;
#pragma unroll
            for (int ni = 0; ni < 4; ni++) {
                const int s = nB + wn + ni * 8 + (lane & 3) * 2;
                const float y0 = siluf(d[mi][ni][rh * 2 + 0] * sc + bi);
                const float y1 = siluf(d[mi][ni][rh * 2 + 1] * sc + bi);
                float2 v; v.x = y0; v.y = y1;
                *(float2*)(OUTP + (size_t)o * HWSZ + s) = v;
                lmx = fmaxf(lmx, fmaxf(y0, y1));
                lsm += y0 + y1;
            }
            lmx = fmaxf(lmx, __shfl_xor_sync(0xffffffffu, lmx, 1));
            lsm += __shfl_xor_sync(0xffffffffu, lsm, 1);
            lmx = fmaxf(lmx, __shfl_xor_sync(0xffffffffu, lmx, 2));
            lsm += __shfl_xor_sync(0xffffffffu, lsm, 2);
            if ((lane & 3) == 0) {
                const int ch = wm + mi * 16 + rh * 8 + (lane >> 2);
                red_mx[ch * 4 + (warp & 3)] = lmx;
                red_sm[ch * 4 + (warp & 3)] = lsm;
            }
        }
    }
    __syncthreads();
    if (tid < 128) {
        float m = red_mx[tid * 4], s = red_sm[tid * 4];
#pragma unroll
        for (int i = 1; i < 4; i++) { m = fmaxf(m, red_mx[tid * 4 + i]); s += red_sm[tid * 4 + i]; }
        const size_t idx = ((size_t)slab * NTILE + blockIdx.x) * CCH + mB + tid;
        g_pmax[idx] = m;
        g_psum[idx] = s;
    }
}

__global__ void k_poolred()
{
    const int slab = blockIdx.x, c = threadIdx.x;
    const int t = slab & 3;
    float mx, sm;
    if (t < 3) {
        const size_t base = (size_t)slab * NTILE * CCH + c;
        mx = -3.402823e38f; sm = 0.f;
#pragma unroll
        for (int i = 0; i < NTILE; i++) {
            mx = fmaxf(mx, g_pmax[base + (size_t)i * CCH]);
            sm += g_psum[base + (size_t)i * CCH];
        }
    } else {
        const int b = slab >> 2;
        mx = g_rmax[b * CCH + c];
        sm = g_rsum[b * CCH + c];
    }
    g_pool[slab * 512 + c] = mx;
    g_pool[slab * 512 + 256 + c] = sm * (1.0f / 4096.0f);
}

__global__ __launch_bounds__(256)
void k_ain(const float* __restrict__ w_in, const float* __restrict__ b_in,
           const float* __restrict__ ptc,  const float* __restrict__ ftc,
           const float* __restrict__ w_tc, const float* __restrict__ b_tc)
{
    const int b = blockIdx.x;
    __shared__ float pool[4][512];
    const int tid = threadIdx.x, lane = tid & 31, warp = tid >> 5;
    for (int i = tid; i < 2048; i += 256)
        ((float*)pool)[i] = g_pool[b * 4 * 512 + i];
    __syncthreads();

    const int o = blockIdx.y * 8 + warp;
    const float* wr = w_in + (size_t)o * 512;
    float a0 = 0.f, a1 = 0.f, a2 = 0.f, a3 = 0.f;
#pragma unroll
    for (int c = lane; c < 512; c += 32) {
        const float w = __ldg(wr + c);
        a0 += w * pool[0][c]; a1 += w * pool[1][c];
        a2 += w * pool[2][c]; a3 += w * pool[3][c];
    }
#pragma unroll
    for (int off = 16; off; off >>= 1) {
        a0 += __shfl_xor_sync(0xffffffffu, a0, off);
        a1 += __shfl_xor_sync(0xffffffffu, a1, off);
        a2 += __shfl_xor_sync(0xffffffffu, a2, off);
        a3 += __shfl_xor_sync(0xffffffffu, a3, off);
    }
    if (lane == 0) {
        const float bi = __ldg(b_in + o), wt = __ldg(w_tc + o), bt = __ldg(b_tc + o);
        g_ain_p[(b * 3 + 0) * CCH + o] = siluf(a0 + bi) + tanhf(__ldg(ptc + b * 3 + 0) * wt + bt);
        g_ain_p[(b * 3 + 1) * CCH + o] = siluf(a1 + bi) + tanhf(__ldg(ptc + b * 3 + 1) * wt + bt);
        g_ain_p[(b * 3 + 2) * CCH + o] = siluf(a2 + bi) + tanhf(__ldg(ptc + b * 3 + 2) * wt + bt);
        const float b3 = siluf(a3 + bi);
#pragma unroll
        for (int f = 0; f < 4; f++)
            g_ain_f[(b * 4 + f) * CCH + o] = b3 + tanhf(__ldg(ftc + b * 4 + f) * wt + bt);
    }
}

__global__ __launch_bounds__(256)
void k_qk2(const float* __restrict__ w_q, const float* __restrict__ b_q,
           const float* __restrict__ w_k, const float* __restrict__ b_k)
{
    const int b = blockIdx.x;
    __shared__ float ainf[4][256], ainp[3][256];
    const int tid = threadIdx.x, lane = tid & 31, warp = tid >> 5;
    for (int i = tid; i < 1024; i += 256) ((float*)ainf)[i] = g_ain_f[b * 4 * CCH + i];
    for (int i = tid; i < 768;  i += 256) ((float*)ainp)[i] = g_ain_p[b * 3 * CCH + i];
    __syncthreads();

    const int o = blockIdx.y * 8 + warp;
    const float* wqr = w_q + (size_t)o * 256;
    const float* wkr = w_k + (size_t)o * 256;
    float q0 = 0.f, q1 = 0.f, q2 = 0.f, q3 = 0.f, k0 = 0.f, k1 = 0.f, k2 = 0.f;
#pragma unroll
    for (int c = lane; c < 256; c += 32) {
        const float wq = __ldg(wqr + c), wk = __ldg(wkr + c);
        q0 += wq * ainf[0][c]; q1 += wq * ainf[1][c];
        q2 += wq * ainf[2][c]; q3 += wq * ainf[3][c];
        k0 += wk * ainp[0][c]; k1 += wk * ainp[1][c]; k2 += wk * ainp[2][c];
    }
#pragma unroll
    for (int off = 16; off; off >>= 1) {
        q0 += __shfl_xor_sync(0xffffffffu, q0, off);
        q1 += __shfl_xor_sync(0xffffffffu, q1, off);
        q2 += __shfl_xor_sync(0xffffffffu, q2, off);
        q3 += __shfl_xor_sync(0xffffffffu, q3, off);
        k0 += __shfl_xor_sync(0xffffffffu, k0, off);
        k1 += __shfl_xor_sync(0xffffffffu, k1, off);
        k2 += __shfl_xor_sync(0xffffffffu, k2, off);
    }
    if (lane == 0) {
        const float bq = __ldg(b_q + o), bk = __ldg(b_k + o);
        g_q[(b * 4 + 0) * CCH + o] = q0 + bq;
        g_q[(b * 4 + 1) * CCH + o] = q1 + bq;
        g_q[(b * 4 + 2) * CCH + o] = q2 + bq;
        g_q[(b * 4 + 3) * CCH + o] = q3 + bq;
        g_k[(b * 3 + 0) * CCH + o] = k0 + bk;
        g_k[(b * 3 + 1) * CCH + o] = k1 + bk;
        g_k[(b * 3 + 2) * CCH + o] = k2 + bk;
    }
}

__global__ __launch_bounds__(384)
void k_coef()
{
    const int b = blockIdx.x;
    const int tid = threadIdx.x, lane = tid & 31, warp = tid >> 5;
    __shared__ float aw[12];
    const int f = warp / 3, p = warp % 3;
    const float* qv = g_q + (b * 4 + f) * CCH;
    const float* kv = g_k + (b * 3 + p) * CCH;
    float acc = 0.f;
#pragma unroll
    for (int c = lane; c < 256; c += 32) acc += qv[c] * kv[c];
#pragma unroll
    for (int off = 16; off; off >>= 1)
        acc += __shfl_xor_sync(0xffffffffu, acc, off);
    if (lane == 0) aw[warp] = acc * 0.5f;
    __syncthreads();
    if (tid < 4) {
        const float a0 = aw[tid * 3 + 0], a1 = aw[tid * 3 + 1], a2 = aw[tid * 3 + 2];
        g_coef[(b * 4 + tid) * 4 + 0] = -a0;
        g_coef[(b * 4 + tid) * 4 + 1] = -a1;
        g_coef[(b * 4 + tid) * 4 + 2] = -a2;
        g_coef[(b * 4 + tid) * 4 + 3] = a0 + a1 + a2;
    }
}

__global__ __launch_bounds__(256)
void k_out(const float* __restrict__ feat, const float* __restrict__ p_attn,
           float* __restrict__ out)
{
    __shared__ float scoef[128];
    if (threadIdx.x < 128) scoef[threadIdx.x] = g_coef[threadIdx.x];
    __syncthreads();
    const int id = blockIdx.x * 256 + threadIdx.x;
    const int b = id >> 18;
    const int rem = id & 0x3FFFF;
    const int c = rem >> 10;
    const float4* f4fp = (const float4*)g_fp;
    const float4* f4ft = (const float4*)feat;
    const float4 last = __ldg(f4ft + ((size_t)(b * 4 + 3) << 18) + rem);
    const float4 p0 = __ldg(f4fp + ((size_t)(b * 4 + 0) << 18) + rem);
    const float4 p1 = __ldg(f4fp + ((size_t)(b * 4 + 1) << 18) + rem);
    const float4 p2 = __ldg(f4fp + ((size_t)(b * 4 + 2) << 18) + rem);
    const float4 p3 = __ldg(f4fp + ((size_t)(b * 4 + 3) << 18) + rem);
    const float ps = __ldg(p_attn + c) * (1.0f / 3.0f);
    float4* o4 = (float4*)out;
#pragma unroll
    for (int f = 0; f < 4; f++) {
        const float* cf = scoef + (b * 4 + f) * 4;
        const float c0 = cf[0], c1 = cf[1], c2 = cf[2], c3 = cf[3];
        float4 r;
        r.x = last.x + ps * (c0 * p0.x + c1 * p1.x + c2 * p2.x + c3 * p3.x);
        r.y = last.y + ps * (c0 * p0.y + c1 * p1.y + c2 * p2.y + c3 * p3.y);
        r.z = last.z + ps * (c0 * p0.z + c1 * p1.z + c2 * p2.z + c3 * p3.z);
        r.w = last.w + ps * (c0 * p0.w + c1 * p1.w + c2 * p2.w + c3 * p3.w);
        o4[((size_t)(b * 4 + f) << 18) + rem] = r;
    }
}

extern "C" void kernel_launch(void* const* d_in, const int* in_sizes, int n_in,
                              void* d_out, int out_size)
{
    (void)in_sizes; (void)n_in; (void)out_size;
    const float* feature = (const float*)d_in[0];
    const float* ptc     = (const float*)d_in[1];
    const float* ftc     = (const float*)d_in[2];
    const float* w_tc    = (const float*)d_in[3];
    const float* b_tc    = (const float*)d_in[4];
    const float* w_in    = (const float*)d_in[5];
    const float* b_in    = (const float*)d_in[6];
    const float* conv_w  = (const float*)d_in[7];
    const float* gma     = (const float*)d_in[8];
    const float* bta     = (const float*)d_in[9];
    const float* mu      = (const float*)d_in[10];
    const float* var     = (const float*)d_in[11];
    const float* w_q     = (const float*)d_in[12];
    const float* b_q     = (const float*)d_in[13];
    const float* w_k     = (const float*)d_in[14];
    const float* b_k     = (const float*)d_in[15];
    const float* p_attn  = (const float*)d_in[16];

    cudaFuncSetAttribute(k_gemm, cudaFuncAttributeMaxDynamicSharedMemorySize, DSMEM);

    k_wconv<<<256, 256>>>(conv_w);
    k_rawpool<<<8 * CCH, 128>>>(feature);
    dim3 g1(NTILE, 2, NSLAB);
    k_gemm<<<g1, 256, DSMEM>>>(feature, gma, bta, mu, var);
    k_poolred<<<NSLAB, 256>>>();
    dim3 g2(8, 32);
    k_ain<<<g2, 256>>>(w_in, b_in, ptc, ftc, w_tc, b_tc);
    k_qk2<<<g2, 256>>>(w_q, b_q, w_k, b_k);
    k_coef<<<8, 384>>>();
    k_out<<<8192, 256>>>(feature, p_attn, (float*)d_out);
}